// round 5
// baseline (speedup 1.0000x reference)
#include <cuda_runtime.h>
#include <math.h>

#define NN 100000
#define NE 3200000
#define NF 512
#define NH 256
#define NC 16
#define NLAYER 8

// ---------------- device scratch (allocation-free rule: __device__ globals) ----
__device__ float g_h  [(size_t)NN * NH];
__device__ float g_h0 [(size_t)NN * NH];
__device__ float g_sup[(size_t)NN * NH];
__device__ int   g_rowptr[NN + 1];
__device__ int   g_cnt[NN];
__device__ int   g_srcs[NE];
__device__ float g_wsort[NE];

// ---------------- CSR build ---------------------------------------------------
__global__ void zero_cnt_kernel(int* __restrict__ cnt) {
    int i = blockIdx.x * blockDim.x + threadIdx.x;
    if (i < NN) cnt[i] = 0;
}

__global__ void hist_kernel(const int* __restrict__ dst, int* __restrict__ cnt) {
    int e = blockIdx.x * blockDim.x + threadIdx.x;
    if (e < NE) atomicAdd(&cnt[dst[e]], 1);
}

// single-block scan: counts (in cnt) -> exclusive offsets in rowptr, and cnt
// becomes the running cursor for the scatter pass.
__global__ __launch_bounds__(1024) void scan_kernel(int* __restrict__ cnt,
                                                    int* __restrict__ rowptr) {
    const int tid  = threadIdx.x;
    const int lane = tid & 31;
    const int wid  = tid >> 5;
    __shared__ int wsum[32];
    int carry = 0;
    for (int base = 0; base < NN; base += 1024) {
        int i = base + tid;
        int v = (i < NN) ? cnt[i] : 0;
        int incl = v;
#pragma unroll
        for (int off = 1; off < 32; off <<= 1) {
            int t = __shfl_up_sync(0xffffffffu, incl, off);
            if (lane >= off) incl += t;
        }
        if (lane == 31) wsum[wid] = incl;
        __syncthreads();
        if (wid == 0) {
            int s = wsum[lane];
#pragma unroll
            for (int off = 1; off < 32; off <<= 1) {
                int t = __shfl_up_sync(0xffffffffu, s, off);
                if (lane >= off) s += t;
            }
            wsum[lane] = s;
        }
        __syncthreads();
        int woff = (wid > 0) ? wsum[wid - 1] : 0;
        int excl = carry + woff + (incl - v);
        if (i < NN) { rowptr[i] = excl; cnt[i] = excl; }
        int total = wsum[31];
        __syncthreads();
        carry += total;
    }
    if (tid == 0) rowptr[NN] = carry;
}

__global__ void scatter_kernel(const int* __restrict__ src,
                               const int* __restrict__ dst,
                               const float* __restrict__ w,
                               int* __restrict__ cur,
                               int* __restrict__ osrc,
                               float* __restrict__ ow) {
    int e = blockIdx.x * blockDim.x + threadIdx.x;
    if (e < NE) {
        int d = dst[e];
        int p = atomicAdd(&cur[d], 1);
        osrc[p] = src[e];
        ow[p]   = w[e];
    }
}

// ---------------- SpMM: warp per row, fused 0.9*agg + 0.1*h0 ------------------
__device__ __forceinline__ void fmav(float4& a, float w, const float4& v) {
    a.x = fmaf(w, v.x, a.x); a.y = fmaf(w, v.y, a.y);
    a.z = fmaf(w, v.z, a.z); a.w = fmaf(w, v.w, a.w);
}

__global__ __launch_bounds__(256) void spmm_kernel(
    const int* __restrict__ rowptr, const int* __restrict__ srcs,
    const float* __restrict__ ws,
    const float* __restrict__ h, const float* __restrict__ h0,
    float* __restrict__ sup) {
    const int warp = threadIdx.x >> 5;
    const int lane = threadIdx.x & 31;
    const int row  = blockIdx.x * 8 + warp;
    if (row >= NN) return;
    const int beg = rowptr[row];
    const int end = rowptr[row + 1];
    float4 acc0 = make_float4(0.f, 0.f, 0.f, 0.f);
    float4 acc1 = acc0;
    const float4* hp = (const float4*)h;
    int e = beg;
    for (; e + 2 <= end; e += 2) {
        int   s0 = srcs[e],  s1 = srcs[e + 1];
        float wa = ws[e],    wb = ws[e + 1];
        const float4* p0 = hp + (size_t)s0 * 64;
        const float4* p1 = hp + (size_t)s1 * 64;
        float4 x0 = p0[lane], x1 = p0[32 + lane];
        float4 y0 = p1[lane], y1 = p1[32 + lane];
        fmav(acc0, wa, x0); fmav(acc1, wa, x1);
        fmav(acc0, wb, y0); fmav(acc1, wb, y1);
    }
    if (e < end) {
        int s0 = srcs[e]; float wa = ws[e];
        const float4* p0 = hp + (size_t)s0 * 64;
        float4 x0 = p0[lane], x1 = p0[32 + lane];
        fmav(acc0, wa, x0); fmav(acc1, wa, x1);
    }
    const float4* r = (const float4*)h0 + (size_t)row * 64;
    float4 r0 = r[lane], r1 = r[32 + lane];
    float4 o0, o1;
    o0.x = fmaf(0.9f, acc0.x, 0.1f * r0.x);
    o0.y = fmaf(0.9f, acc0.y, 0.1f * r0.y);
    o0.z = fmaf(0.9f, acc0.z, 0.1f * r0.z);
    o0.w = fmaf(0.9f, acc0.w, 0.1f * r0.w);
    o1.x = fmaf(0.9f, acc1.x, 0.1f * r1.x);
    o1.y = fmaf(0.9f, acc1.y, 0.1f * r1.y);
    o1.z = fmaf(0.9f, acc1.z, 0.1f * r1.z);
    o1.w = fmaf(0.9f, acc1.w, 0.1f * r1.w);
    float4* sp = (float4*)sup + (size_t)row * 64;
    sp[lane]      = o0;
    sp[32 + lane] = o1;
}

// ---------------- GEMM: 128x128x8 tiles, fma.rn.f32x2 (full-rate fp32) --------
#define BM 128
#define BN 128
#define BK 8

union F4U { float4 f; unsigned long long u[2]; };

// mode 0: h = h0 = relu(A@B + bias)            (A = x, K = 512)
// mode 1: h = relu(theta*(A@B) + (1-theta)*A + h)   (A = support, K = 256)
__global__ __launch_bounds__(256, 2) void gemm_kernel(
    const float* __restrict__ A, const float* __restrict__ B, int M, int K,
    const float* __restrict__ bias, const float* __restrict__ sup,
    float* __restrict__ hout, float* __restrict__ h0out,
    float theta, int mode) {
    __shared__ __align__(16) float Asd[2][BK][2 * BM];  // A duplicated pairwise
    __shared__ __align__(16) float Bs [2][BK][BN];

    const int tid = threadIdx.x;
    const int tx  = tid & 15;
    const int ty  = tid >> 4;
    const int rowBase = blockIdx.x * BM;
    const int nBase   = blockIdx.y * BN;

    const int aRow = tid >> 1;
    const int aCol = (tid & 1) * 4;
    const int bRow = tid >> 5;
    const int bCol = (tid & 31) * 4;

    unsigned long long acc[8][4];
#pragma unroll
    for (int i = 0; i < 8; i++)
#pragma unroll
        for (int j = 0; j < 4; j++) acc[i][j] = 0ULL;

    const int nk = K / BK;
    const float4 z4 = make_float4(0.f, 0.f, 0.f, 0.f);

    {   // tile 0
        int gr = rowBase + aRow;
        float4 av = (gr < M) ? *(const float4*)(A + (size_t)gr * K + aCol) : z4;
        float4 bv = *(const float4*)(B + (size_t)bRow * NH + nBase + bCol);
        float2 d;
        d.x = d.y = av.x; *(float2*)&Asd[0][aCol + 0][2 * aRow] = d;
        d.x = d.y = av.y; *(float2*)&Asd[0][aCol + 1][2 * aRow] = d;
        d.x = d.y = av.z; *(float2*)&Asd[0][aCol + 2][2 * aRow] = d;
        d.x = d.y = av.w; *(float2*)&Asd[0][aCol + 3][2 * aRow] = d;
        *(float4*)&Bs[0][bRow][bCol] = bv;
    }
    __syncthreads();

    for (int kt = 0; kt < nk; ++kt) {
        const int buf = kt & 1;
        float4 aN = z4, bN = z4;
        if (kt + 1 < nk) {
            int kb = (kt + 1) * BK;
            int gr = rowBase + aRow;
            aN = (gr < M) ? *(const float4*)(A + (size_t)gr * K + kb + aCol) : z4;
            bN = *(const float4*)(B + (size_t)(kb + bRow) * NH + nBase + bCol);
        }
#pragma unroll
        for (int k = 0; k < BK; ++k) {
            F4U a0, a1, a2, a3, b0, b1;
            const float4* ap4 = (const float4*)&Asd[buf][k][ty * 16];
            a0.f = ap4[0]; a1.f = ap4[1]; a2.f = ap4[2]; a3.f = ap4[3];
            const float4* bp4 = (const float4*)&Bs[buf][k][tx * 8];
            b0.f = bp4[0]; b1.f = bp4[1];
            unsigned long long av[8] = {a0.u[0], a0.u[1], a1.u[0], a1.u[1],
                                        a2.u[0], a2.u[1], a3.u[0], a3.u[1]};
            unsigned long long bv[4] = {b0.u[0], b0.u[1], b1.u[0], b1.u[1]};
#pragma unroll
            for (int i = 0; i < 8; i++)
#pragma unroll
                for (int j = 0; j < 4; j++)
                    asm("fma.rn.f32x2 %0, %1, %2, %0;"
                        : "+l"(acc[i][j]) : "l"(av[i]), "l"(bv[j]));
        }
        if (kt + 1 < nk) {
            const int nb = buf ^ 1;
            float2 d;
            d.x = d.y = aN.x; *(float2*)&Asd[nb][aCol + 0][2 * aRow] = d;
            d.x = d.y = aN.y; *(float2*)&Asd[nb][aCol + 1][2 * aRow] = d;
            d.x = d.y = aN.z; *(float2*)&Asd[nb][aCol + 2][2 * aRow] = d;
            d.x = d.y = aN.w; *(float2*)&Asd[nb][aCol + 3][2 * aRow] = d;
            *(float4*)&Bs[nb][bRow][bCol] = bN;
            __syncthreads();
        }
    }

    const float omt = 1.0f - theta;
#pragma unroll
    for (int i = 0; i < 8; i++) {
        int grow = rowBase + ty * 8 + i;
        if (grow >= M) break;
        size_t rb = (size_t)grow * NH + nBase + tx * 8;
        if (mode == 0) {
#pragma unroll
            for (int j = 0; j < 4; j++) {
                float lo = __uint_as_float((unsigned)(acc[i][j]));
                float hi = __uint_as_float((unsigned)(acc[i][j] >> 32));
                int gc = nBase + tx * 8 + 2 * j;
                float v0 = fmaxf(lo + __ldg(&bias[gc]),     0.f);
                float v1 = fmaxf(hi + __ldg(&bias[gc + 1]), 0.f);
                float2 val = make_float2(v0, v1);
                *(float2*)(hout  + rb + 2 * j) = val;
                *(float2*)(h0out + rb + 2 * j) = val;
            }
        } else {
#pragma unroll
            for (int j = 0; j < 4; j++) {
                float lo = __uint_as_float((unsigned)(acc[i][j]));
                float hi = __uint_as_float((unsigned)(acc[i][j] >> 32));
                float2 s  = *(const float2*)(sup  + rb + 2 * j);
                float2 ho = *(const float2*)(hout + rb + 2 * j);
                float v0 = fmaxf(fmaf(theta, lo, fmaf(omt, s.x, ho.x)), 0.f);
                float v1 = fmaxf(fmaf(theta, hi, fmaf(omt, s.y, ho.y)), 0.f);
                *(float2*)(hout + rb + 2 * j) = make_float2(v0, v1);
            }
        }
    }
}

// ---------------- final fc + sigmoid ------------------------------------------
__global__ __launch_bounds__(128) void fc1_kernel(const float* __restrict__ h,
                                                  const float* __restrict__ w1,
                                                  const float* __restrict__ b1,
                                                  float* __restrict__ out) {
    __shared__ float ws[NH * NC];
    __shared__ float bs[NC];
    const int tid = threadIdx.x;
    for (int i = tid; i < NH * NC; i += 128) ws[i] = w1[i];
    if (tid < NC) bs[tid] = b1[tid];
    __syncthreads();
    const int col = tid & 15;
    const int r   = tid >> 4;
    const int row = blockIdx.x * 8 + r;
    if (row >= NN) return;
    const float* hr = h + (size_t)row * NH;
    float acc = 0.f;
#pragma unroll 4
    for (int k = 0; k < NH; k += 4) {
        float4 hv = *(const float4*)(hr + k);
        acc = fmaf(hv.x, ws[(k + 0) * NC + col], acc);
        acc = fmaf(hv.y, ws[(k + 1) * NC + col], acc);
        acc = fmaf(hv.z, ws[(k + 2) * NC + col], acc);
        acc = fmaf(hv.w, ws[(k + 3) * NC + col], acc);
    }
    acc += bs[col];
    out[(size_t)row * NC + col] = 1.0f / (1.0f + expf(-acc));
}

// ---------------- launch -------------------------------------------------------
extern "C" void kernel_launch(void* const* d_in, const int* in_sizes, int n_in,
                              void* d_out, int out_size) {
    const float* x     = (const float*)d_in[0];
    const int*   esrc  = (const int*)  d_in[1];
    const int*   edst  = (const int*)  d_in[2];
    const float* ew    = (const float*)d_in[3];
    const float* w0    = (const float*)d_in[4];
    const float* b0    = (const float*)d_in[5];
    const float* convw = (const float*)d_in[6];
    const float* w1    = (const float*)d_in[7];
    const float* b1    = (const float*)d_in[8];
    float* out = (float*)d_out;

    void *ph, *ph0, *psup, *prp, *pcnt, *psrc, *pws;
    cudaGetSymbolAddress(&ph,   g_h);
    cudaGetSymbolAddress(&ph0,  g_h0);
    cudaGetSymbolAddress(&psup, g_sup);
    cudaGetSymbolAddress(&prp,  g_rowptr);
    cudaGetSymbolAddress(&pcnt, g_cnt);
    cudaGetSymbolAddress(&psrc, g_srcs);
    cudaGetSymbolAddress(&pws,  g_wsort);
    float* h      = (float*)ph;
    float* h0     = (float*)ph0;
    float* sup    = (float*)psup;
    int*   rowptr = (int*)prp;
    int*   cnt    = (int*)pcnt;
    int*   srcs   = (int*)psrc;
    float* wsort  = (float*)pws;

    // CSR-by-dst build (deterministic up to fp-add order within a row)
    zero_cnt_kernel<<<(NN + 255) / 256, 256>>>(cnt);
    hist_kernel    <<<(NE + 255) / 256, 256>>>(edst, cnt);
    scan_kernel    <<<1, 1024>>>(cnt, rowptr);
    scatter_kernel <<<(NE + 255) / 256, 256>>>(esrc, edst, ew, cnt, srcs, wsort);

    dim3 gg((NN + BM - 1) / BM, NH / BN);

    // h = h0 = relu(x @ w0 + b0)
    gemm_kernel<<<gg, 256>>>(x, w0, NN, NF, b0, nullptr, h, h0, 0.f, 0);

    for (int i = 0; i < NLAYER; ++i) {
        // support = 0.9 * spmm(h) + 0.1 * h0
        spmm_kernel<<<(NN + 7) / 8, 256>>>(rowptr, srcs, wsort, h, h0, sup);
        float theta = (float)log(0.5 / (double)(i + 1) + 1.0);
        // h = relu(theta*(support@W_i) + (1-theta)*support + h)
        gemm_kernel<<<gg, 256>>>(sup, convw + (size_t)i * NH * NH, NN, NH,
                                 nullptr, sup, h, nullptr, theta, 1);
    }

    // out = sigmoid(h @ w1 + b1)
    fc1_kernel<<<(NN + 7) / 8, 128>>>(h, w1, b1, out);
}

// round 7
// speedup vs baseline: 1.3526x; 1.3526x over previous
#include <cuda_runtime.h>
#include <cuda_bf16.h>
#include <math.h>
#include <stdint.h>

#define NN 100000
#define NE 3200000
#define NF 512
#define NH 256
#define NC 16
#define NLAYER 8

// ---------------- device scratch (allocation-free rule: __device__ globals) ----
__device__ float g_h  [(size_t)NN * NH];
__device__ float g_h0 [(size_t)NN * NH];
__device__ float g_sup[(size_t)NN * NH];
__device__ int   g_rowptr[NN + 1];
__device__ int   g_cnt[NN];
__device__ int   g_srcs[NE];
__device__ float g_wsort[NE];
// pre-transposed, bf16 hi/lo split weights: conv [8][N=256][K=256], fc0 [N=256][K=512]
__device__ __nv_bfloat16 g_wth[(size_t)NLAYER * NH * NH];
__device__ __nv_bfloat16 g_wtl[(size_t)NLAYER * NH * NH];
__device__ __nv_bfloat16 g_w0h[(size_t)NH * NF];
__device__ __nv_bfloat16 g_w0l[(size_t)NH * NF];

// ---------------- CSR build ---------------------------------------------------
__global__ void zero_cnt_kernel(int* __restrict__ cnt) {
    int i = blockIdx.x * blockDim.x + threadIdx.x;
    if (i < NN) cnt[i] = 0;
}

__global__ void hist_kernel(const int* __restrict__ dst, int* __restrict__ cnt) {
    int e = blockIdx.x * blockDim.x + threadIdx.x;
    if (e < NE) atomicAdd(&cnt[dst[e]], 1);
}

__global__ __launch_bounds__(1024) void scan_kernel(int* __restrict__ cnt,
                                                    int* __restrict__ rowptr) {
    const int tid  = threadIdx.x;
    const int lane = tid & 31;
    const int wid  = tid >> 5;
    __shared__ int wsum[32];
    int carry = 0;
    for (int base = 0; base < NN; base += 1024) {
        int i = base + tid;
        int v = (i < NN) ? cnt[i] : 0;
        int incl = v;
#pragma unroll
        for (int off = 1; off < 32; off <<= 1) {
            int t = __shfl_up_sync(0xffffffffu, incl, off);
            if (lane >= off) incl += t;
        }
        if (lane == 31) wsum[wid] = incl;
        __syncthreads();
        if (wid == 0) {
            int s = wsum[lane];
#pragma unroll
            for (int off = 1; off < 32; off <<= 1) {
                int t = __shfl_up_sync(0xffffffffu, s, off);
                if (lane >= off) s += t;
            }
            wsum[lane] = s;
        }
        __syncthreads();
        int woff = (wid > 0) ? wsum[wid - 1] : 0;
        int excl = carry + woff + (incl - v);
        if (i < NN) { rowptr[i] = excl; cnt[i] = excl; }
        int total = wsum[31];
        __syncthreads();
        carry += total;
    }
    if (tid == 0) rowptr[NN] = carry;
}

__global__ void scatter_kernel(const int* __restrict__ src,
                               const int* __restrict__ dst,
                               const float* __restrict__ w,
                               int* __restrict__ cur,
                               int* __restrict__ osrc,
                               float* __restrict__ ow) {
    int e = blockIdx.x * blockDim.x + threadIdx.x;
    if (e < NE) {
        int d = dst[e];
        int p = atomicAdd(&cur[d], 1);
        osrc[p] = src[e];
        ow[p]   = w[e];
    }
}

// ---------------- weight transpose + bf16 hi/lo split --------------------------
__global__ void prep_w_kernel(const float* __restrict__ w0,
                              const float* __restrict__ convw,
                              __nv_bfloat16* __restrict__ w0h,
                              __nv_bfloat16* __restrict__ w0l,
                              __nv_bfloat16* __restrict__ wth,
                              __nv_bfloat16* __restrict__ wtl) {
    int i = blockIdx.x * blockDim.x + threadIdx.x;
    if (i < NH * NF) {           // w0^T: [n][k], k stride 512
        int n = i >> 9, k = i & 511;
        float f = w0[(size_t)k * NH + n];
        __nv_bfloat16 h = __float2bfloat16(f);
        w0h[i] = h;
        w0l[i] = __float2bfloat16(f - __bfloat162float(h));
    }
    if (i < NLAYER * NH * NH) {  // conv_w[l]^T: [n][k], k stride 256
        int l = i >> 16, nk = i & 65535, n = nk >> 8, k = nk & 255;
        float f = convw[(size_t)l * 65536 + (size_t)k * NH + n];
        __nv_bfloat16 h = __float2bfloat16(f);
        wth[i] = h;
        wtl[i] = __float2bfloat16(f - __bfloat162float(h));
    }
}

// ---------------- SpMM: warp per row, fused 0.9*agg + 0.1*h0 ------------------
__device__ __forceinline__ void fmav(float4& a, float w, const float4& v) {
    a.x = fmaf(w, v.x, a.x); a.y = fmaf(w, v.y, a.y);
    a.z = fmaf(w, v.z, a.z); a.w = fmaf(w, v.w, a.w);
}

__global__ __launch_bounds__(256) void spmm_kernel(
    const int* __restrict__ rowptr, const int* __restrict__ srcs,
    const float* __restrict__ ws,
    const float* __restrict__ h, const float* __restrict__ h0,
    float* __restrict__ sup) {
    const int warp = threadIdx.x >> 5;
    const int lane = threadIdx.x & 31;
    const int row  = blockIdx.x * 8 + warp;
    if (row >= NN) return;
    const int beg = rowptr[row];
    const int end = rowptr[row + 1];
    float4 acc0 = make_float4(0.f, 0.f, 0.f, 0.f);
    float4 acc1 = acc0;
    const float4* hp = (const float4*)h;
    int e = beg;
    for (; e + 2 <= end; e += 2) {
        int   s0 = srcs[e],  s1 = srcs[e + 1];
        float wa = ws[e],    wb = ws[e + 1];
        const float4* p0 = hp + (size_t)s0 * 64;
        const float4* p1 = hp + (size_t)s1 * 64;
        float4 x0 = p0[lane], x1 = p0[32 + lane];
        float4 y0 = p1[lane], y1 = p1[32 + lane];
        fmav(acc0, wa, x0); fmav(acc1, wa, x1);
        fmav(acc0, wb, y0); fmav(acc1, wb, y1);
    }
    if (e < end) {
        int s0 = srcs[e]; float wa = ws[e];
        const float4* p0 = hp + (size_t)s0 * 64;
        float4 x0 = p0[lane], x1 = p0[32 + lane];
        fmav(acc0, wa, x0); fmav(acc1, wa, x1);
    }
    const float4* r = (const float4*)h0 + (size_t)row * 64;
    float4 r0 = r[lane], r1 = r[32 + lane];
    float4 o0, o1;
    o0.x = fmaf(0.9f, acc0.x, 0.1f * r0.x);
    o0.y = fmaf(0.9f, acc0.y, 0.1f * r0.y);
    o0.z = fmaf(0.9f, acc0.z, 0.1f * r0.z);
    o0.w = fmaf(0.9f, acc0.w, 0.1f * r0.w);
    o1.x = fmaf(0.9f, acc1.x, 0.1f * r1.x);
    o1.y = fmaf(0.9f, acc1.y, 0.1f * r1.y);
    o1.z = fmaf(0.9f, acc1.z, 0.1f * r1.z);
    o1.w = fmaf(0.9f, acc1.w, 0.1f * r1.w);
    float4* sp = (float4*)sup + (size_t)row * 64;
    sp[lane]      = o0;
    sp[32 + lane] = o1;
}

// ---------------- mma.sync bf16 GEMM: 128x128 tile, hi/lo split (3 MMAs) ------
// mode 0: h = h0 = relu(A@B + bias)                       (A = x, K = 512)
// mode 1: h = relu(theta*(A@B) + (1-theta)*sup + h)       (A = sup, K = 256)
// B pre-transposed K-major bf16: Bh/Bl[n][k], row stride K.
#define BM 128
#define BN 128
#define BKC 64
// smem: 4 tiles of 128 rows x 128B (SW128-swizzled)
#define SA_H 0
#define SA_L 16384
#define SB_H 32768
#define SB_L 49152
#define GEMM_SMEM 65536

__device__ __forceinline__ uint32_t smem_u32(const void* p) {
    uint32_t a;
    asm("{ .reg .u64 t; cvta.to.shared.u64 t, %1; cvt.u32.u64 %0, t; }" : "=r"(a) : "l"(p));
    return a;
}

__device__ __forceinline__ void ldsm_x4(uint32_t* r, uint32_t addr) {
    asm volatile("ldmatrix.sync.aligned.m8n8.x4.shared.b16 {%0,%1,%2,%3}, [%4];"
                 : "=r"(r[0]), "=r"(r[1]), "=r"(r[2]), "=r"(r[3]) : "r"(addr));
}
__device__ __forceinline__ void ldsm_x2(uint32_t* r, uint32_t addr) {
    asm volatile("ldmatrix.sync.aligned.m8n8.x2.shared.b16 {%0,%1}, [%2];"
                 : "=r"(r[0]), "=r"(r[1]) : "r"(addr));
}
__device__ __forceinline__ void mma_bf16(float* d, const uint32_t* a, const uint32_t* b) {
    asm volatile("mma.sync.aligned.m16n8k16.row.col.f32.bf16.bf16.f32 "
                 "{%0,%1,%2,%3}, {%4,%5,%6,%7}, {%8,%9}, {%0,%1,%2,%3};"
                 : "+f"(d[0]), "+f"(d[1]), "+f"(d[2]), "+f"(d[3])
                 : "r"(a[0]), "r"(a[1]), "r"(a[2]), "r"(a[3]), "r"(b[0]), "r"(b[1]));
}

__global__ __launch_bounds__(256, 1) void gemm_mma_kernel(
    const float* __restrict__ A, int M, int K,
    const __nv_bfloat16* __restrict__ Bh, const __nv_bfloat16* __restrict__ Bl,
    const float* __restrict__ bias, const float* __restrict__ sup,
    float* __restrict__ hout, float* __restrict__ h0out,
    float theta, int mode) {
    extern __shared__ char smem[];
    const uint32_t sb = smem_u32(smem);
    const int tid  = threadIdx.x;
    const int warp = tid >> 5;
    const int lane = tid & 31;
    const int wm = warp & 1;    // M warp: 0..1 -> 64 rows each
    const int wn = warp >> 1;   // N warp: 0..3 -> 32 cols each
    const int rowBase = blockIdx.x * BM;
    const int nBase   = blockIdx.y * BN;

    float acc[4][4][4];
#pragma unroll
    for (int i = 0; i < 4; i++)
#pragma unroll
        for (int j = 0; j < 4; j++)
#pragma unroll
            for (int r = 0; r < 4; r++) acc[i][j][r] = 0.f;

    // fill indices
    const int frow = tid >> 3;   // 0..31 (+32*j)
    const int fc8  = tid & 7;    // 8-element (16B bf16 / 32B fp32) unit

    for (int kb = 0; kb < K; kb += BKC) {
        // ---- fill A: fp32 -> bf16 hi/lo split, SW128 swizzled ----
#pragma unroll
        for (int j = 0; j < 4; ++j) {
            int row = frow + 32 * j;
            int grow = rowBase + row;
            float4 v0 = make_float4(0.f, 0.f, 0.f, 0.f), v1 = v0;
            if (grow < M) {
                const float* ap = A + (size_t)grow * K + kb + fc8 * 8;
                v0 = *(const float4*)ap;
                v1 = *(const float4*)(ap + 4);
            }
            __nv_bfloat162 h01 = __floats2bfloat162_rn(v0.x, v0.y);
            __nv_bfloat162 h23 = __floats2bfloat162_rn(v0.z, v0.w);
            __nv_bfloat162 h45 = __floats2bfloat162_rn(v1.x, v1.y);
            __nv_bfloat162 h67 = __floats2bfloat162_rn(v1.z, v1.w);
            float2 f01 = __bfloat1622float2(h01);
            float2 f23 = __bfloat1622float2(h23);
            float2 f45 = __bfloat1622float2(h45);
            float2 f67 = __bfloat1622float2(h67);
            __nv_bfloat162 l01 = __floats2bfloat162_rn(v0.x - f01.x, v0.y - f01.y);
            __nv_bfloat162 l23 = __floats2bfloat162_rn(v0.z - f23.x, v0.w - f23.y);
            __nv_bfloat162 l45 = __floats2bfloat162_rn(v1.x - f45.x, v1.y - f45.y);
            __nv_bfloat162 l67 = __floats2bfloat162_rn(v1.z - f67.x, v1.w - f67.y);
            uint32_t off = (uint32_t)(row * 128 + ((fc8 ^ (row & 7)) << 4));
            uint4 uh, ul;
            uh.x = *(uint32_t*)&h01; uh.y = *(uint32_t*)&h23;
            uh.z = *(uint32_t*)&h45; uh.w = *(uint32_t*)&h67;
            ul.x = *(uint32_t*)&l01; ul.y = *(uint32_t*)&l23;
            ul.z = *(uint32_t*)&l45; ul.w = *(uint32_t*)&l67;
            *(uint4*)(smem + SA_H + off) = uh;
            *(uint4*)(smem + SA_L + off) = ul;
        }
        // ---- fill B: pre-split bf16 [n][K], SW128 swizzled ----
#pragma unroll
        for (int j = 0; j < 4; ++j) {
            int n = frow + 32 * j;
            size_t gi = (size_t)(nBase + n) * K + kb + fc8 * 8;
            uint32_t off = (uint32_t)(n * 128 + ((fc8 ^ (n & 7)) << 4));
            *(uint4*)(smem + SB_H + off) = *(const uint4*)(Bh + gi);
            *(uint4*)(smem + SB_L + off) = *(const uint4*)(Bl + gi);
        }
        __syncthreads();

        // ---- compute: 4 k16 steps ----
#pragma unroll
        for (int ks = 0; ks < 4; ++ks) {
            const int u0 = ks * 2;
            uint32_t ah[4][4], al[4][4], bh[4][2], bl[4][2];
#pragma unroll
            for (int mt = 0; mt < 4; ++mt) {
                int row  = wm * 64 + mt * 16 + (lane & 15);
                int unit = u0 + (lane >> 4);
                uint32_t off = (uint32_t)(row * 128 + ((unit ^ (row & 7)) << 4));
                ldsm_x4(ah[mt], sb + SA_H + off);
                ldsm_x4(al[mt], sb + SA_L + off);
            }
#pragma unroll
            for (int nt = 0; nt < 4; ++nt) {
                int n    = wn * 32 + nt * 8 + (lane & 7);
                int unit = u0 + ((lane >> 3) & 1);
                uint32_t off = (uint32_t)(n * 128 + ((unit ^ (n & 7)) << 4));
                ldsm_x2(bh[nt], sb + SB_H + off);
                ldsm_x2(bl[nt], sb + SB_L + off);
            }
#pragma unroll
            for (int mt = 0; mt < 4; ++mt)
#pragma unroll
                for (int nt = 0; nt < 4; ++nt) {
                    mma_bf16(acc[mt][nt], ah[mt], bh[nt]);
                    mma_bf16(acc[mt][nt], ah[mt], bl[nt]);
                    mma_bf16(acc[mt][nt], al[mt], bh[nt]);
                }
        }
        __syncthreads();
    }

    // ---- epilogue ----
    const float omt = 1.0f - theta;
    const int r0 = rowBase + wm * 64 + (lane >> 2);
    const int c0 = nBase + wn * 32 + 2 * (lane & 3);
#pragma unroll
    for (int mt = 0; mt < 4; ++mt) {
#pragma unroll
        for (int half = 0; half < 2; ++half) {
            int grow = r0 + mt * 16 + half * 8;
            if (grow >= M) continue;
#pragma unroll
            for (int nt = 0; nt < 4; ++nt) {
                float d0 = acc[mt][nt][half * 2 + 0];
                float d1 = acc[mt][nt][half * 2 + 1];
                int gc = c0 + nt * 8;
                size_t gi = (size_t)grow * NH + gc;
                if (mode == 0) {
                    float v0 = fmaxf(d0 + __ldg(&bias[gc]),     0.f);
                    float v1 = fmaxf(d1 + __ldg(&bias[gc + 1]), 0.f);
                    float2 v = make_float2(v0, v1);
                    *(float2*)(hout  + gi) = v;
                    *(float2*)(h0out + gi) = v;
                } else {
                    float2 s  = *(const float2*)(sup  + gi);
                    float2 ho = *(const float2*)(hout + gi);
                    float v0 = fmaxf(fmaf(theta, d0, fmaf(omt, s.x, ho.x)), 0.f);
                    float v1 = fmaxf(fmaf(theta, d1, fmaf(omt, s.y, ho.y)), 0.f);
                    *(float2*)(hout + gi) = make_float2(v0, v1);
                }
            }
        }
    }
}

// ---------------- final fc + sigmoid ------------------------------------------
__global__ __launch_bounds__(128) void fc1_kernel(const float* __restrict__ h,
                                                  const float* __restrict__ w1,
                                                  const float* __restrict__ b1,
                                                  float* __restrict__ out) {
    __shared__ float ws[NH * NC];
    __shared__ float bs[NC];
    const int tid = threadIdx.x;
    for (int i = tid; i < NH * NC; i += 128) ws[i] = w1[i];
    if (tid < NC) bs[tid] = b1[tid];
    __syncthreads();
    const int col = tid & 15;
    const int r   = tid >> 4;
    const int row = blockIdx.x * 8 + r;
    if (row >= NN) return;
    const float* hr = h + (size_t)row * NH;
    float acc = 0.f;
#pragma unroll 4
    for (int k = 0; k < NH; k += 4) {
        float4 hv = *(const float4*)(hr + k);
        acc = fmaf(hv.x, ws[(k + 0) * NC + col], acc);
        acc = fmaf(hv.y, ws[(k + 1) * NC + col], acc);
        acc = fmaf(hv.z, ws[(k + 2) * NC + col], acc);
        acc = fmaf(hv.w, ws[(k + 3) * NC + col], acc);
    }
    acc += bs[col];
    out[(size_t)row * NC + col] = 1.0f / (1.0f + expf(-acc));
}

// ---------------- launch -------------------------------------------------------
extern "C" void kernel_launch(void* const* d_in, const int* in_sizes, int n_in,
                              void* d_out, int out_size) {
    const float* x     = (const float*)d_in[0];
    const int*   esrc  = (const int*)  d_in[1];
    const int*   edst  = (const int*)  d_in[2];
    const float* ew    = (const float*)d_in[3];
    const float* w0    = (const float*)d_in[4];
    const float* b0    = (const float*)d_in[5];
    const float* convw = (const float*)d_in[6];
    const float* w1    = (const float*)d_in[7];
    const float* b1    = (const float*)d_in[8];
    float* out = (float*)d_out;

    void *ph, *ph0, *psup, *prp, *pcnt, *psrc, *pws;
    void *pwth, *pwtl, *pw0h, *pw0l;
    cudaGetSymbolAddress(&ph,   g_h);
    cudaGetSymbolAddress(&ph0,  g_h0);
    cudaGetSymbolAddress(&psup, g_sup);
    cudaGetSymbolAddress(&prp,  g_rowptr);
    cudaGetSymbolAddress(&pcnt, g_cnt);
    cudaGetSymbolAddress(&psrc, g_srcs);
    cudaGetSymbolAddress(&pws,  g_wsort);
    cudaGetSymbolAddress(&pwth, g_wth);
    cudaGetSymbolAddress(&pwtl, g_wtl);
    cudaGetSymbolAddress(&pw0h, g_w0h);
    cudaGetSymbolAddress(&pw0l, g_w0l);
    float* h      = (float*)ph;
    float* h0     = (float*)ph0;
    float* sup    = (float*)psup;
    int*   rowptr = (int*)prp;
    int*   cnt    = (int*)pcnt;
    int*   srcs   = (int*)psrc;
    float* wsort  = (float*)pws;
    __nv_bfloat16* wth = (__nv_bfloat16*)pwth;
    __nv_bfloat16* wtl = (__nv_bfloat16*)pwtl;
    __nv_bfloat16* w0h = (__nv_bfloat16*)pw0h;
    __nv_bfloat16* w0l = (__nv_bfloat16*)pw0l;

    cudaFuncSetAttribute(gemm_mma_kernel,
                         cudaFuncAttributeMaxDynamicSharedMemorySize, GEMM_SMEM);

    // CSR-by-dst build
    zero_cnt_kernel<<<(NN + 255) / 256, 256>>>(cnt);
    hist_kernel    <<<(NE + 255) / 256, 256>>>(edst, cnt);
    scan_kernel    <<<1, 1024>>>(cnt, rowptr);
    scatter_kernel <<<(NE + 255) / 256, 256>>>(esrc, edst, ew, cnt, srcs, wsort);

    // weight transpose + bf16 hi/lo split
    prep_w_kernel<<<(NLAYER * NH * NH + 255) / 256, 256>>>(w0, convw, w0h, w0l, wth, wtl);

    dim3 gg((NN + BM - 1) / BM, NH / BN);

    // h = h0 = relu(x @ w0 + b0)
    gemm_mma_kernel<<<gg, 256, GEMM_SMEM>>>(x, NN, NF, w0h, w0l, b0,
                                            nullptr, h, h0, 0.f, 0);

    for (int i = 0; i < NLAYER; ++i) {
        // support = 0.9 * spmm(h) + 0.1 * h0
        spmm_kernel<<<(NN + 7) / 8, 256>>>(rowptr, srcs, wsort, h, h0, sup);
        float theta = (float)log(0.5 / (double)(i + 1) + 1.0);
        // h = relu(theta*(support@W_i) + (1-theta)*support + h)
        gemm_mma_kernel<<<gg, 256, GEMM_SMEM>>>(sup, NN, NH,
                                                wth + (size_t)i * NH * NH,
                                                wtl + (size_t)i * NH * NH,
                                                nullptr, sup, h, nullptr, theta, 1);
    }

    // out = sigmoid(h @ w1 + b1)
    fc1_kernel<<<(NN + 7) / 8, 128>>>(h, w1, b1, out);
}

// round 8
// speedup vs baseline: 1.4418x; 1.0660x over previous
#include <cuda_runtime.h>
#include <cuda_bf16.h>
#include <math.h>
#include <stdint.h>

#define NN 100000
#define NE 3200000
#define NF 512
#define NH 256
#define NC 16
#define NLAYER 8

// ---------------- device scratch (allocation-free rule: __device__ globals) ----
__device__ float g_h  [(size_t)NN * NH];
__device__ float g_h0 [(size_t)NN * NH];
__device__ float g_sup[(size_t)NN * NH];
__device__ int   g_rowptr[NN + 1];
__device__ int   g_cnt[NN];
__device__ int   g_srcs[NE];
__device__ float g_wsort[NE];
// pre-transposed, bf16 hi/lo split weights: conv [8][N=256][K=256], fc0 [N=256][K=512]
__device__ __nv_bfloat16 g_wth[(size_t)NLAYER * NH * NH];
__device__ __nv_bfloat16 g_wtl[(size_t)NLAYER * NH * NH];
__device__ __nv_bfloat16 g_w0h[(size_t)NH * NF];
__device__ __nv_bfloat16 g_w0l[(size_t)NH * NF];

// ---------------- CSR build ---------------------------------------------------
__global__ void zero_cnt_kernel(int* __restrict__ cnt) {
    int i = blockIdx.x * blockDim.x + threadIdx.x;
    if (i < NN) cnt[i] = 0;
}

__global__ void hist_kernel(const int* __restrict__ dst, int* __restrict__ cnt) {
    int e = blockIdx.x * blockDim.x + threadIdx.x;
    if (e < NE) atomicAdd(&cnt[dst[e]], 1);
}

__global__ __launch_bounds__(1024) void scan_kernel(int* __restrict__ cnt,
                                                    int* __restrict__ rowptr) {
    const int tid  = threadIdx.x;
    const int lane = tid & 31;
    const int wid  = tid >> 5;
    __shared__ int wsum[32];
    int carry = 0;
    for (int base = 0; base < NN; base += 1024) {
        int i = base + tid;
        int v = (i < NN) ? cnt[i] : 0;
        int incl = v;
#pragma unroll
        for (int off = 1; off < 32; off <<= 1) {
            int t = __shfl_up_sync(0xffffffffu, incl, off);
            if (lane >= off) incl += t;
        }
        if (lane == 31) wsum[wid] = incl;
        __syncthreads();
        if (wid == 0) {
            int s = wsum[lane];
#pragma unroll
            for (int off = 1; off < 32; off <<= 1) {
                int t = __shfl_up_sync(0xffffffffu, s, off);
                if (lane >= off) s += t;
            }
            wsum[lane] = s;
        }
        __syncthreads();
        int woff = (wid > 0) ? wsum[wid - 1] : 0;
        int excl = carry + woff + (incl - v);
        if (i < NN) { rowptr[i] = excl; cnt[i] = excl; }
        int total = wsum[31];
        __syncthreads();
        carry += total;
    }
    if (tid == 0) rowptr[NN] = carry;
}

__global__ void scatter_kernel(const int* __restrict__ src,
                               const int* __restrict__ dst,
                               const float* __restrict__ w,
                               int* __restrict__ cur,
                               int* __restrict__ osrc,
                               float* __restrict__ ow) {
    int e = blockIdx.x * blockDim.x + threadIdx.x;
    if (e < NE) {
        int d = dst[e];
        int p = atomicAdd(&cur[d], 1);
        osrc[p] = src[e];
        ow[p]   = w[e];
    }
}

// ---------------- weight transpose + bf16 hi/lo split --------------------------
__global__ void prep_w_kernel(const float* __restrict__ w0,
                              const float* __restrict__ convw,
                              __nv_bfloat16* __restrict__ w0h,
                              __nv_bfloat16* __restrict__ w0l,
                              __nv_bfloat16* __restrict__ wth,
                              __nv_bfloat16* __restrict__ wtl) {
    int i = blockIdx.x * blockDim.x + threadIdx.x;
    if (i < NH * NF) {           // w0^T: [n][k], k stride 512
        int n = i >> 9, k = i & 511;
        float f = w0[(size_t)k * NH + n];
        __nv_bfloat16 h = __float2bfloat16(f);
        w0h[i] = h;
        w0l[i] = __float2bfloat16(f - __bfloat162float(h));
    }
    if (i < NLAYER * NH * NH) {  // conv_w[l]^T: [n][k], k stride 256
        int l = i >> 16, nk = i & 65535, n = nk >> 8, k = nk & 255;
        float f = convw[(size_t)l * 65536 + (size_t)k * NH + n];
        __nv_bfloat16 h = __float2bfloat16(f);
        wth[i] = h;
        wtl[i] = __float2bfloat16(f - __bfloat162float(h));
    }
}

// ---------------- SpMM: warp per row, half the features per pass ---------------
// Column-split so the gathered half of h (51 MB of touched cache lines) stays
// L2-resident; h0/sup streams use .cs evict-first so they don't evict h.
__device__ __forceinline__ void fmav(float4& a, float w, const float4& v) {
    a.x = fmaf(w, v.x, a.x); a.y = fmaf(w, v.y, a.y);
    a.z = fmaf(w, v.z, a.z); a.w = fmaf(w, v.w, a.w);
}

__global__ __launch_bounds__(256) void spmm_half_kernel(
    const int* __restrict__ rowptr, const int* __restrict__ srcs,
    const float* __restrict__ ws,
    const float* __restrict__ h, const float* __restrict__ h0,
    float* __restrict__ sup, int col4) {
    const int warp = threadIdx.x >> 5;
    const int lane = threadIdx.x & 31;
    const int row  = blockIdx.x * 8 + warp;
    if (row >= NN) return;
    int e = rowptr[row];
    const int end = rowptr[row + 1];
    const float4* hp = (const float4*)h + col4 + lane;
    float4 acc = make_float4(0.f, 0.f, 0.f, 0.f);
    for (; e + 4 <= end; e += 4) {
        int   s0 = __ldg(srcs + e),     s1 = __ldg(srcs + e + 1);
        int   s2 = __ldg(srcs + e + 2), s3 = __ldg(srcs + e + 3);
        float w0 = __ldg(ws + e),       w1 = __ldg(ws + e + 1);
        float w2 = __ldg(ws + e + 2),   w3 = __ldg(ws + e + 3);
        float4 v0 = hp[(size_t)s0 * 64];
        float4 v1 = hp[(size_t)s1 * 64];
        float4 v2 = hp[(size_t)s2 * 64];
        float4 v3 = hp[(size_t)s3 * 64];
        fmav(acc, w0, v0); fmav(acc, w1, v1);
        fmav(acc, w2, v2); fmav(acc, w3, v3);
    }
    for (; e < end; ++e) {
        int s = __ldg(srcs + e);
        float w = __ldg(ws + e);
        fmav(acc, w, hp[(size_t)s * 64]);
    }
    const size_t oi = (size_t)row * 64 + col4 + lane;
    float4 r = __ldcs((const float4*)h0 + oi);
    float4 o;
    o.x = fmaf(0.9f, acc.x, 0.1f * r.x);
    o.y = fmaf(0.9f, acc.y, 0.1f * r.y);
    o.z = fmaf(0.9f, acc.z, 0.1f * r.z);
    o.w = fmaf(0.9f, acc.w, 0.1f * r.w);
    __stcs((float4*)sup + oi, o);
}

// ---------------- mma.sync bf16 GEMM: 128x128 tile, hi/lo split (3 MMAs) ------
// mode 0: h = h0 = relu(A@B + bias)                       (A = x, K = 512)
// mode 1: h = relu(theta*(A@B) + (1-theta)*sup + h)       (A = sup, K = 256)
// B pre-transposed K-major bf16: Bh/Bl[n][k], row stride K.
#define BM 128
#define BN 128
#define BKC 64
// smem: 4 tiles of 128 rows x 128B (SW128-swizzled)
#define SA_H 0
#define SA_L 16384
#define SB_H 32768
#define SB_L 49152
#define GEMM_SMEM 65536

__device__ __forceinline__ uint32_t smem_u32(const void* p) {
    uint32_t a;
    asm("{ .reg .u64 t; cvta.to.shared.u64 t, %1; cvt.u32.u64 %0, t; }" : "=r"(a) : "l"(p));
    return a;
}

__device__ __forceinline__ void ldsm_x4(uint32_t* r, uint32_t addr) {
    asm volatile("ldmatrix.sync.aligned.m8n8.x4.shared.b16 {%0,%1,%2,%3}, [%4];"
                 : "=r"(r[0]), "=r"(r[1]), "=r"(r[2]), "=r"(r[3]) : "r"(addr));
}
__device__ __forceinline__ void ldsm_x2(uint32_t* r, uint32_t addr) {
    asm volatile("ldmatrix.sync.aligned.m8n8.x2.shared.b16 {%0,%1}, [%2];"
                 : "=r"(r[0]), "=r"(r[1]) : "r"(addr));
}
__device__ __forceinline__ void mma_bf16(float* d, const uint32_t* a, const uint32_t* b) {
    asm volatile("mma.sync.aligned.m16n8k16.row.col.f32.bf16.bf16.f32 "
                 "{%0,%1,%2,%3}, {%4,%5,%6,%7}, {%8,%9}, {%0,%1,%2,%3};"
                 : "+f"(d[0]), "+f"(d[1]), "+f"(d[2]), "+f"(d[3])
                 : "r"(a[0]), "r"(a[1]), "r"(a[2]), "r"(a[3]), "r"(b[0]), "r"(b[1]));
}

__global__ __launch_bounds__(256, 1) void gemm_mma_kernel(
    const float* __restrict__ A, int M, int K,
    const __nv_bfloat16* __restrict__ Bh, const __nv_bfloat16* __restrict__ Bl,
    const float* __restrict__ bias, const float* __restrict__ sup,
    float* __restrict__ hout, float* __restrict__ h0out,
    float theta, int mode) {
    extern __shared__ char smem[];
    const uint32_t sb = smem_u32(smem);
    const int tid  = threadIdx.x;
    const int warp = tid >> 5;
    const int lane = tid & 31;
    const int wm = warp & 1;    // M warp: 0..1 -> 64 rows each
    const int wn = warp >> 1;   // N warp: 0..3 -> 32 cols each
    const int rowBase = blockIdx.x * BM;
    const int nBase   = blockIdx.y * BN;

    float acc[4][4][4];
#pragma unroll
    for (int i = 0; i < 4; i++)
#pragma unroll
        for (int j = 0; j < 4; j++)
#pragma unroll
            for (int r = 0; r < 4; r++) acc[i][j][r] = 0.f;

    // fill indices
    const int frow = tid >> 3;   // 0..31 (+32*j)
    const int fc8  = tid & 7;    // 8-element (16B bf16 / 32B fp32) unit

    for (int kb = 0; kb < K; kb += BKC) {
        // ---- fill A: fp32 -> bf16 hi/lo split, SW128 swizzled ----
#pragma unroll
        for (int j = 0; j < 4; ++j) {
            int row = frow + 32 * j;
            int grow = rowBase + row;
            float4 v0 = make_float4(0.f, 0.f, 0.f, 0.f), v1 = v0;
            if (grow < M) {
                const float* ap = A + (size_t)grow * K + kb + fc8 * 8;
                v0 = *(const float4*)ap;
                v1 = *(const float4*)(ap + 4);
            }
            __nv_bfloat162 h01 = __floats2bfloat162_rn(v0.x, v0.y);
            __nv_bfloat162 h23 = __floats2bfloat162_rn(v0.z, v0.w);
            __nv_bfloat162 h45 = __floats2bfloat162_rn(v1.x, v1.y);
            __nv_bfloat162 h67 = __floats2bfloat162_rn(v1.z, v1.w);
            float2 f01 = __bfloat1622float2(h01);
            float2 f23 = __bfloat1622float2(h23);
            float2 f45 = __bfloat1622float2(h45);
            float2 f67 = __bfloat1622float2(h67);
            __nv_bfloat162 l01 = __floats2bfloat162_rn(v0.x - f01.x, v0.y - f01.y);
            __nv_bfloat162 l23 = __floats2bfloat162_rn(v0.z - f23.x, v0.w - f23.y);
            __nv_bfloat162 l45 = __floats2bfloat162_rn(v1.x - f45.x, v1.y - f45.y);
            __nv_bfloat162 l67 = __floats2bfloat162_rn(v1.z - f67.x, v1.w - f67.y);
            uint32_t off = (uint32_t)(row * 128 + ((fc8 ^ (row & 7)) << 4));
            uint4 uh, ul;
            uh.x = *(uint32_t*)&h01; uh.y = *(uint32_t*)&h23;
            uh.z = *(uint32_t*)&h45; uh.w = *(uint32_t*)&h67;
            ul.x = *(uint32_t*)&l01; ul.y = *(uint32_t*)&l23;
            ul.z = *(uint32_t*)&l45; ul.w = *(uint32_t*)&l67;
            *(uint4*)(smem + SA_H + off) = uh;
            *(uint4*)(smem + SA_L + off) = ul;
        }
        // ---- fill B: pre-split bf16 [n][K], SW128 swizzled ----
#pragma unroll
        for (int j = 0; j < 4; ++j) {
            int n = frow + 32 * j;
            size_t gi = (size_t)(nBase + n) * K + kb + fc8 * 8;
            uint32_t off = (uint32_t)(n * 128 + ((fc8 ^ (n & 7)) << 4));
            *(uint4*)(smem + SB_H + off) = *(const uint4*)(Bh + gi);
            *(uint4*)(smem + SB_L + off) = *(const uint4*)(Bl + gi);
        }
        __syncthreads();

        // ---- compute: 4 k16 steps ----
#pragma unroll
        for (int ks = 0; ks < 4; ++ks) {
            const int u0 = ks * 2;
            uint32_t ah[4][4], al[4][4], bh[4][2], bl[4][2];
#pragma unroll
            for (int mt = 0; mt < 4; ++mt) {
                int row  = wm * 64 + mt * 16 + (lane & 15);
                int unit = u0 + (lane >> 4);
                uint32_t off = (uint32_t)(row * 128 + ((unit ^ (row & 7)) << 4));
                ldsm_x4(ah[mt], sb + SA_H + off);
                ldsm_x4(al[mt], sb + SA_L + off);
            }
#pragma unroll
            for (int nt = 0; nt < 4; ++nt) {
                int n    = wn * 32 + nt * 8 + (lane & 7);
                int unit = u0 + ((lane >> 3) & 1);
                uint32_t off = (uint32_t)(n * 128 + ((unit ^ (n & 7)) << 4));
                ldsm_x2(bh[nt], sb + SB_H + off);
                ldsm_x2(bl[nt], sb + SB_L + off);
            }
#pragma unroll
            for (int mt = 0; mt < 4; ++mt)
#pragma unroll
                for (int nt = 0; nt < 4; ++nt) {
                    mma_bf16(acc[mt][nt], ah[mt], bh[nt]);
                    mma_bf16(acc[mt][nt], ah[mt], bl[nt]);
                    mma_bf16(acc[mt][nt], al[mt], bh[nt]);
                }
        }
        __syncthreads();
    }

    // ---- epilogue ----
    const float omt = 1.0f - theta;
    const int r0 = rowBase + wm * 64 + (lane >> 2);
    const int c0 = nBase + wn * 32 + 2 * (lane & 3);
#pragma unroll
    for (int mt = 0; mt < 4; ++mt) {
#pragma unroll
        for (int half = 0; half < 2; ++half) {
            int grow = r0 + mt * 16 + half * 8;
            if (grow >= M) continue;
#pragma unroll
            for (int nt = 0; nt < 4; ++nt) {
                float d0 = acc[mt][nt][half * 2 + 0];
                float d1 = acc[mt][nt][half * 2 + 1];
                int gc = c0 + nt * 8;
                size_t gi = (size_t)grow * NH + gc;
                if (mode == 0) {
                    float v0 = fmaxf(d0 + __ldg(&bias[gc]),     0.f);
                    float v1 = fmaxf(d1 + __ldg(&bias[gc + 1]), 0.f);
                    float2 v = make_float2(v0, v1);
                    *(float2*)(hout  + gi) = v;
                    *(float2*)(h0out + gi) = v;
                } else {
                    float2 s  = *(const float2*)(sup  + gi);
                    float2 ho = *(const float2*)(hout + gi);
                    float v0 = fmaxf(fmaf(theta, d0, fmaf(omt, s.x, ho.x)), 0.f);
                    float v1 = fmaxf(fmaf(theta, d1, fmaf(omt, s.y, ho.y)), 0.f);
                    *(float2*)(hout + gi) = make_float2(v0, v1);
                }
            }
        }
    }
}

// ---------------- final fc + sigmoid ------------------------------------------
__global__ __launch_bounds__(128) void fc1_kernel(const float* __restrict__ h,
                                                  const float* __restrict__ w1,
                                                  const float* __restrict__ b1,
                                                  float* __restrict__ out) {
    __shared__ float ws[NH * NC];
    __shared__ float bs[NC];
    const int tid = threadIdx.x;
    for (int i = tid; i < NH * NC; i += 128) ws[i] = w1[i];
    if (tid < NC) bs[tid] = b1[tid];
    __syncthreads();
    const int col = tid & 15;
    const int r   = tid >> 4;
    const int row = blockIdx.x * 8 + r;
    if (row >= NN) return;
    const float* hr = h + (size_t)row * NH;
    float acc = 0.f;
#pragma unroll 4
    for (int k = 0; k < NH; k += 4) {
        float4 hv = *(const float4*)(hr + k);
        acc = fmaf(hv.x, ws[(k + 0) * NC + col], acc);
        acc = fmaf(hv.y, ws[(k + 1) * NC + col], acc);
        acc = fmaf(hv.z, ws[(k + 2) * NC + col], acc);
        acc = fmaf(hv.w, ws[(k + 3) * NC + col], acc);
    }
    acc += bs[col];
    out[(size_t)row * NC + col] = 1.0f / (1.0f + expf(-acc));
}

// ---------------- launch -------------------------------------------------------
extern "C" void kernel_launch(void* const* d_in, const int* in_sizes, int n_in,
                              void* d_out, int out_size) {
    const float* x     = (const float*)d_in[0];
    const int*   esrc  = (const int*)  d_in[1];
    const int*   edst  = (const int*)  d_in[2];
    const float* ew    = (const float*)d_in[3];
    const float* w0    = (const float*)d_in[4];
    const float* b0    = (const float*)d_in[5];
    const float* convw = (const float*)d_in[6];
    const float* w1    = (const float*)d_in[7];
    const float* b1    = (const float*)d_in[8];
    float* out = (float*)d_out;

    void *ph, *ph0, *psup, *prp, *pcnt, *psrc, *pws;
    void *pwth, *pwtl, *pw0h, *pw0l;
    cudaGetSymbolAddress(&ph,   g_h);
    cudaGetSymbolAddress(&ph0,  g_h0);
    cudaGetSymbolAddress(&psup, g_sup);
    cudaGetSymbolAddress(&prp,  g_rowptr);
    cudaGetSymbolAddress(&pcnt, g_cnt);
    cudaGetSymbolAddress(&psrc, g_srcs);
    cudaGetSymbolAddress(&pws,  g_wsort);
    cudaGetSymbolAddress(&pwth, g_wth);
    cudaGetSymbolAddress(&pwtl, g_wtl);
    cudaGetSymbolAddress(&pw0h, g_w0h);
    cudaGetSymbolAddress(&pw0l, g_w0l);
    float* h      = (float*)ph;
    float* h0     = (float*)ph0;
    float* sup    = (float*)psup;
    int*   rowptr = (int*)prp;
    int*   cnt    = (int*)pcnt;
    int*   srcs   = (int*)psrc;
    float* wsort  = (float*)pws;
    __nv_bfloat16* wth = (__nv_bfloat16*)pwth;
    __nv_bfloat16* wtl = (__nv_bfloat16*)pwtl;
    __nv_bfloat16* w0h = (__nv_bfloat16*)pw0h;
    __nv_bfloat16* w0l = (__nv_bfloat16*)pw0l;

    cudaFuncSetAttribute(gemm_mma_kernel,
                         cudaFuncAttributeMaxDynamicSharedMemorySize, GEMM_SMEM);

    // CSR-by-dst build
    zero_cnt_kernel<<<(NN + 255) / 256, 256>>>(cnt);
    hist_kernel    <<<(NE + 255) / 256, 256>>>(edst, cnt);
    scan_kernel    <<<1, 1024>>>(cnt, rowptr);
    scatter_kernel <<<(NE + 255) / 256, 256>>>(esrc, edst, ew, cnt, srcs, wsort);

    // weight transpose + bf16 hi/lo split
    prep_w_kernel<<<(NLAYER * NH * NH + 255) / 256, 256>>>(w0, convw, w0h, w0l, wth, wtl);

    dim3 gg((NN + BM - 1) / BM, NH / BN);
    const int sgrid = (NN + 7) / 8;

    // h = h0 = relu(x @ w0 + b0)
    gemm_mma_kernel<<<gg, 256, GEMM_SMEM>>>(x, NN, NF, w0h, w0l, b0,
                                            nullptr, h, h0, 0.f, 0);

    for (int i = 0; i < NLAYER; ++i) {
        // support = 0.9 * spmm(h) + 0.1 * h0  (two sequential half-feature passes
        // so each pass's gathered h lines stay L2-resident)
        spmm_half_kernel<<<sgrid, 256>>>(rowptr, srcs, wsort, h, h0, sup, 0);
        spmm_half_kernel<<<sgrid, 256>>>(rowptr, srcs, wsort, h, h0, sup, 32);
        float theta = (float)log(0.5 / (double)(i + 1) + 1.0);
        // h = relu(theta*(support@W_i) + (1-theta)*support + h)
        gemm_mma_kernel<<<gg, 256, GEMM_SMEM>>>(sup, NN, NH,
                                                wth + (size_t)i * NH * NH,
                                                wtl + (size_t)i * NH * NH,
                                                nullptr, sup, h, nullptr, theta, 1);
    }

    // out = sigmoid(h @ w1 + b1)
    fc1_kernel<<<(NN + 7) / 8, 128>>>(h, w1, b1, out);
}

// round 9
// speedup vs baseline: 1.4434x; 1.0011x over previous
#include <cuda_runtime.h>
#include <cuda_bf16.h>
#include <math.h>
#include <stdint.h>

#define NN 100000
#define NE 3200000
#define NF 512
#define NH 256
#define NC 16
#define NLAYER 8

// ---------------- device scratch (allocation-free rule: __device__ globals) ----
__device__ float g_h  [(size_t)NN * NH];
__device__ float g_h0 [(size_t)NN * NH];
__device__ float g_sup[(size_t)NN * NH];
__device__ int   g_rowptr[NN + 1];
__device__ int   g_cnt[NN];
__device__ int   g_srcs[NE];
__device__ float g_wsort[NE];
// pre-transposed, bf16 hi/lo split weights: conv [8][N=256][K=256], fc0 [N=256][K=512]
__device__ __nv_bfloat16 g_wth[(size_t)NLAYER * NH * NH];
__device__ __nv_bfloat16 g_wtl[(size_t)NLAYER * NH * NH];
__device__ __nv_bfloat16 g_w0h[(size_t)NH * NF];
__device__ __nv_bfloat16 g_w0l[(size_t)NH * NF];

// ---------------- CSR build ---------------------------------------------------
__global__ void zero_cnt_kernel(int* __restrict__ cnt) {
    int i = blockIdx.x * blockDim.x + threadIdx.x;
    if (i < NN) cnt[i] = 0;
}

__global__ void hist_kernel(const int* __restrict__ dst, int* __restrict__ cnt) {
    int e = blockIdx.x * blockDim.x + threadIdx.x;
    if (e < NE) atomicAdd(&cnt[dst[e]], 1);
}

__global__ __launch_bounds__(1024) void scan_kernel(int* __restrict__ cnt,
                                                    int* __restrict__ rowptr) {
    const int tid  = threadIdx.x;
    const int lane = tid & 31;
    const int wid  = tid >> 5;
    __shared__ int wsum[32];
    int carry = 0;
    for (int base = 0; base < NN; base += 1024) {
        int i = base + tid;
        int v = (i < NN) ? cnt[i] : 0;
        int incl = v;
#pragma unroll
        for (int off = 1; off < 32; off <<= 1) {
            int t = __shfl_up_sync(0xffffffffu, incl, off);
            if (lane >= off) incl += t;
        }
        if (lane == 31) wsum[wid] = incl;
        __syncthreads();
        if (wid == 0) {
            int s = wsum[lane];
#pragma unroll
            for (int off = 1; off < 32; off <<= 1) {
                int t = __shfl_up_sync(0xffffffffu, s, off);
                if (lane >= off) s += t;
            }
            wsum[lane] = s;
        }
        __syncthreads();
        int woff = (wid > 0) ? wsum[wid - 1] : 0;
        int excl = carry + woff + (incl - v);
        if (i < NN) { rowptr[i] = excl; cnt[i] = excl; }
        int total = wsum[31];
        __syncthreads();
        carry += total;
    }
    if (tid == 0) rowptr[NN] = carry;
}

__global__ void scatter_kernel(const int* __restrict__ src,
                               const int* __restrict__ dst,
                               const float* __restrict__ w,
                               int* __restrict__ cur,
                               int* __restrict__ osrc,
                               float* __restrict__ ow) {
    int e = blockIdx.x * blockDim.x + threadIdx.x;
    if (e < NE) {
        int d = dst[e];
        int p = atomicAdd(&cur[d], 1);
        osrc[p] = src[e];
        ow[p]   = w[e];
    }
}

// ---------------- weight transpose + bf16 hi/lo split --------------------------
__global__ void prep_w_kernel(const float* __restrict__ w0,
                              const float* __restrict__ convw,
                              __nv_bfloat16* __restrict__ w0h,
                              __nv_bfloat16* __restrict__ w0l,
                              __nv_bfloat16* __restrict__ wth,
                              __nv_bfloat16* __restrict__ wtl) {
    int i = blockIdx.x * blockDim.x + threadIdx.x;
    if (i < NH * NF) {           // w0^T: [n][k], k stride 512
        int n = i >> 9, k = i & 511;
        float f = w0[(size_t)k * NH + n];
        __nv_bfloat16 h = __float2bfloat16(f);
        w0h[i] = h;
        w0l[i] = __float2bfloat16(f - __bfloat162float(h));
    }
    if (i < NLAYER * NH * NH) {  // conv_w[l]^T: [n][k], k stride 256
        int l = i >> 16, nk = i & 65535, n = nk >> 8, k = nk & 255;
        float f = convw[(size_t)l * 65536 + (size_t)k * NH + n];
        __nv_bfloat16 h = __float2bfloat16(f);
        wth[i] = h;
        wtl[i] = __float2bfloat16(f - __bfloat162float(h));
    }
}

// ---------------- SpMM: warp per row, half the features per pass ---------------
// Column-split so the gathered half of h (51 MB of touched cache lines) stays
// L2-resident; h0/sup streams use .cs evict-first so they don't evict h.
__device__ __forceinline__ void fmav(float4& a, float w, const float4& v) {
    a.x = fmaf(w, v.x, a.x); a.y = fmaf(w, v.y, a.y);
    a.z = fmaf(w, v.z, a.z); a.w = fmaf(w, v.w, a.w);
}

__global__ __launch_bounds__(256) void spmm_half_kernel(
    const int* __restrict__ rowptr, const int* __restrict__ srcs,
    const float* __restrict__ ws,
    const float* __restrict__ h, const float* __restrict__ h0,
    float* __restrict__ sup, int col4) {
    const int warp = threadIdx.x >> 5;
    const int lane = threadIdx.x & 31;
    const int row  = blockIdx.x * 8 + warp;
    if (row >= NN) return;
    int e = rowptr[row];
    const int end = rowptr[row + 1];
    const float4* hp = (const float4*)h + col4 + lane;
    float4 acc = make_float4(0.f, 0.f, 0.f, 0.f);
    for (; e + 4 <= end; e += 4) {
        int   s0 = __ldg(srcs + e),     s1 = __ldg(srcs + e + 1);
        int   s2 = __ldg(srcs + e + 2), s3 = __ldg(srcs + e + 3);
        float w0 = __ldg(ws + e),       w1 = __ldg(ws + e + 1);
        float w2 = __ldg(ws + e + 2),   w3 = __ldg(ws + e + 3);
        float4 v0 = hp[(size_t)s0 * 64];
        float4 v1 = hp[(size_t)s1 * 64];
        float4 v2 = hp[(size_t)s2 * 64];
        float4 v3 = hp[(size_t)s3 * 64];
        fmav(acc, w0, v0); fmav(acc, w1, v1);
        fmav(acc, w2, v2); fmav(acc, w3, v3);
    }
    for (; e < end; ++e) {
        int s = __ldg(srcs + e);
        float w = __ldg(ws + e);
        fmav(acc, w, hp[(size_t)s * 64]);
    }
    const size_t oi = (size_t)row * 64 + col4 + lane;
    float4 r = __ldcs((const float4*)h0 + oi);
    float4 o;
    o.x = fmaf(0.9f, acc.x, 0.1f * r.x);
    o.y = fmaf(0.9f, acc.y, 0.1f * r.y);
    o.z = fmaf(0.9f, acc.z, 0.1f * r.z);
    o.w = fmaf(0.9f, acc.w, 0.1f * r.w);
    __stcs((float4*)sup + oi, o);
}

// ---------------- mma.sync bf16 GEMM: 128x128 tile, hi/lo split (3 MMAs) ------
// mode 0: h = h0 = relu(A@B + bias)                       (A = x, K = 512)
// mode 1: h = relu(theta*(A@B) + (1-theta)*sup + h)       (A = sup, K = 256)
// B pre-transposed K-major bf16: Bh/Bl[n][k], row stride K.
#define BM 128
#define BN 128
#define BKC 64
// smem: 4 tiles of 128 rows x 128B (SW128-swizzled)
#define SA_H 0
#define SA_L 16384
#define SB_H 32768
#define SB_L 49152
#define GEMM_SMEM 65536

__device__ __forceinline__ uint32_t smem_u32(const void* p) {
    uint32_t a;
    asm("{ .reg .u64 t; cvta.to.shared.u64 t, %1; cvt.u32.u64 %0, t; }" : "=r"(a) : "l"(p));
    return a;
}

__device__ __forceinline__ void ldsm_x4(uint32_t* r, uint32_t addr) {
    asm volatile("ldmatrix.sync.aligned.m8n8.x4.shared.b16 {%0,%1,%2,%3}, [%4];"
                 : "=r"(r[0]), "=r"(r[1]), "=r"(r[2]), "=r"(r[3]) : "r"(addr));
}
__device__ __forceinline__ void ldsm_x2(uint32_t* r, uint32_t addr) {
    asm volatile("ldmatrix.sync.aligned.m8n8.x2.shared.b16 {%0,%1}, [%2];"
                 : "=r"(r[0]), "=r"(r[1]) : "r"(addr));
}
__device__ __forceinline__ void mma_bf16(float* d, const uint32_t* a, const uint32_t* b) {
    asm volatile("mma.sync.aligned.m16n8k16.row.col.f32.bf16.bf16.f32 "
                 "{%0,%1,%2,%3}, {%4,%5,%6,%7}, {%8,%9}, {%0,%1,%2,%3};"
                 : "+f"(d[0]), "+f"(d[1]), "+f"(d[2]), "+f"(d[3])
                 : "r"(a[0]), "r"(a[1]), "r"(a[2]), "r"(a[3]), "r"(b[0]), "r"(b[1]));
}

__global__ __launch_bounds__(256, 1) void gemm_mma_kernel(
    const float* __restrict__ A, int M, int K,
    const __nv_bfloat16* __restrict__ Bh, const __nv_bfloat16* __restrict__ Bl,
    const float* __restrict__ bias, const float* __restrict__ sup,
    float* __restrict__ hout, float* __restrict__ h0out,
    float theta, int mode) {
    extern __shared__ char smem[];
    const uint32_t sb = smem_u32(smem);
    const int tid  = threadIdx.x;
    const int warp = tid >> 5;
    const int lane = tid & 31;
    const int wm = warp & 1;    // M warp: 0..1 -> 64 rows each
    const int wn = warp >> 1;   // N warp: 0..3 -> 32 cols each
    const int rowBase = blockIdx.x * BM;
    const int nBase   = blockIdx.y * BN;

    float acc[4][4][4];
#pragma unroll
    for (int i = 0; i < 4; i++)
#pragma unroll
        for (int j = 0; j < 4; j++)
#pragma unroll
            for (int r = 0; r < 4; r++) acc[i][j][r] = 0.f;

    // fill indices
    const int frow = tid >> 3;   // 0..31 (+32*j)
    const int fc8  = tid & 7;    // 8-element (16B bf16 / 32B fp32) unit

    for (int kb = 0; kb < K; kb += BKC) {
        // ---- fill A: fp32 -> bf16 hi/lo split, SW128 swizzled ----
#pragma unroll
        for (int j = 0; j < 4; ++j) {
            int row = frow + 32 * j;
            int grow = rowBase + row;
            float4 v0 = make_float4(0.f, 0.f, 0.f, 0.f), v1 = v0;
            if (grow < M) {
                const float* ap = A + (size_t)grow * K + kb + fc8 * 8;
                v0 = *(const float4*)ap;
                v1 = *(const float4*)(ap + 4);
            }
            __nv_bfloat162 h01 = __floats2bfloat162_rn(v0.x, v0.y);
            __nv_bfloat162 h23 = __floats2bfloat162_rn(v0.z, v0.w);
            __nv_bfloat162 h45 = __floats2bfloat162_rn(v1.x, v1.y);
            __nv_bfloat162 h67 = __floats2bfloat162_rn(v1.z, v1.w);
            float2 f01 = __bfloat1622float2(h01);
            float2 f23 = __bfloat1622float2(h23);
            float2 f45 = __bfloat1622float2(h45);
            float2 f67 = __bfloat1622float2(h67);
            __nv_bfloat162 l01 = __floats2bfloat162_rn(v0.x - f01.x, v0.y - f01.y);
            __nv_bfloat162 l23 = __floats2bfloat162_rn(v0.z - f23.x, v0.w - f23.y);
            __nv_bfloat162 l45 = __floats2bfloat162_rn(v1.x - f45.x, v1.y - f45.y);
            __nv_bfloat162 l67 = __floats2bfloat162_rn(v1.z - f67.x, v1.w - f67.y);
            uint32_t off = (uint32_t)(row * 128 + ((fc8 ^ (row & 7)) << 4));
            uint4 uh, ul;
            uh.x = *(uint32_t*)&h01; uh.y = *(uint32_t*)&h23;
            uh.z = *(uint32_t*)&h45; uh.w = *(uint32_t*)&h67;
            ul.x = *(uint32_t*)&l01; ul.y = *(uint32_t*)&l23;
            ul.z = *(uint32_t*)&l45; ul.w = *(uint32_t*)&l67;
            *(uint4*)(smem + SA_H + off) = uh;
            *(uint4*)(smem + SA_L + off) = ul;
        }
        // ---- fill B: pre-split bf16 [n][K], SW128 swizzled ----
#pragma unroll
        for (int j = 0; j < 4; ++j) {
            int n = frow + 32 * j;
            size_t gi = (size_t)(nBase + n) * K + kb + fc8 * 8;
            uint32_t off = (uint32_t)(n * 128 + ((fc8 ^ (n & 7)) << 4));
            *(uint4*)(smem + SB_H + off) = *(const uint4*)(Bh + gi);
            *(uint4*)(smem + SB_L + off) = *(const uint4*)(Bl + gi);
        }
        __syncthreads();

        // ---- compute: 4 k16 steps ----
#pragma unroll
        for (int ks = 0; ks < 4; ++ks) {
            const int u0 = ks * 2;
            uint32_t ah[4][4], al[4][4], bh[4][2], bl[4][2];
#pragma unroll
            for (int mt = 0; mt < 4; ++mt) {
                int row  = wm * 64 + mt * 16 + (lane & 15);
                int unit = u0 + (lane >> 4);
                uint32_t off = (uint32_t)(row * 128 + ((unit ^ (row & 7)) << 4));
                ldsm_x4(ah[mt], sb + SA_H + off);
                ldsm_x4(al[mt], sb + SA_L + off);
            }
#pragma unroll
            for (int nt = 0; nt < 4; ++nt) {
                int n    = wn * 32 + nt * 8 + (lane & 7);
                int unit = u0 + ((lane >> 3) & 1);
                uint32_t off = (uint32_t)(n * 128 + ((unit ^ (n & 7)) << 4));
                ldsm_x2(bh[nt], sb + SB_H + off);
                ldsm_x2(bl[nt], sb + SB_L + off);
            }
#pragma unroll
            for (int mt = 0; mt < 4; ++mt)
#pragma unroll
                for (int nt = 0; nt < 4; ++nt) {
                    mma_bf16(acc[mt][nt], ah[mt], bh[nt]);
                    mma_bf16(acc[mt][nt], ah[mt], bl[nt]);
                    mma_bf16(acc[mt][nt], al[mt], bh[nt]);
                }
        }
        __syncthreads();
    }

    // ---- epilogue ----
    const float omt = 1.0f - theta;
    const int r0 = rowBase + wm * 64 + (lane >> 2);
    const int c0 = nBase + wn * 32 + 2 * (lane & 3);
#pragma unroll
    for (int mt = 0; mt < 4; ++mt) {
#pragma unroll
        for (int half = 0; half < 2; ++half) {
            int grow = r0 + mt * 16 + half * 8;
            if (grow >= M) continue;
#pragma unroll
            for (int nt = 0; nt < 4; ++nt) {
                float d0 = acc[mt][nt][half * 2 + 0];
                float d1 = acc[mt][nt][half * 2 + 1];
                int gc = c0 + nt * 8;
                size_t gi = (size_t)grow * NH + gc;
                if (mode == 0) {
                    float v0 = fmaxf(d0 + __ldg(&bias[gc]),     0.f);
                    float v1 = fmaxf(d1 + __ldg(&bias[gc + 1]), 0.f);
                    float2 v = make_float2(v0, v1);
                    *(float2*)(hout  + gi) = v;
                    *(float2*)(h0out + gi) = v;
                } else {
                    float2 s  = *(const float2*)(sup  + gi);
                    float2 ho = *(const float2*)(hout + gi);
                    float v0 = fmaxf(fmaf(theta, d0, fmaf(omt, s.x, ho.x)), 0.f);
                    float v1 = fmaxf(fmaf(theta, d1, fmaf(omt, s.y, ho.y)), 0.f);
                    *(float2*)(hout + gi) = make_float2(v0, v1);
                }
            }
        }
    }
}

// ---------------- final fc + sigmoid ------------------------------------------
__global__ __launch_bounds__(128) void fc1_kernel(const float* __restrict__ h,
                                                  const float* __restrict__ w1,
                                                  const float* __restrict__ b1,
                                                  float* __restrict__ out) {
    __shared__ float ws[NH * NC];
    __shared__ float bs[NC];
    const int tid = threadIdx.x;
    for (int i = tid; i < NH * NC; i += 128) ws[i] = w1[i];
    if (tid < NC) bs[tid] = b1[tid];
    __syncthreads();
    const int col = tid & 15;
    const int r   = tid >> 4;
    const int row = blockIdx.x * 8 + r;
    if (row >= NN) return;
    const float* hr = h + (size_t)row * NH;
    float acc = 0.f;
#pragma unroll 4
    for (int k = 0; k < NH; k += 4) {
        float4 hv = *(const float4*)(hr + k);
        acc = fmaf(hv.x, ws[(k + 0) * NC + col], acc);
        acc = fmaf(hv.y, ws[(k + 1) * NC + col], acc);
        acc = fmaf(hv.z, ws[(k + 2) * NC + col], acc);
        acc = fmaf(hv.w, ws[(k + 3) * NC + col], acc);
    }
    acc += bs[col];
    out[(size_t)row * NC + col] = 1.0f / (1.0f + expf(-acc));
}

// ---------------- launch -------------------------------------------------------
extern "C" void kernel_launch(void* const* d_in, const int* in_sizes, int n_in,
                              void* d_out, int out_size) {
    const float* x     = (const float*)d_in[0];
    const int*   esrc  = (const int*)  d_in[1];
    const int*   edst  = (const int*)  d_in[2];
    const float* ew    = (const float*)d_in[3];
    const float* w0    = (const float*)d_in[4];
    const float* b0    = (const float*)d_in[5];
    const float* convw = (const float*)d_in[6];
    const float* w1    = (const float*)d_in[7];
    const float* b1    = (const float*)d_in[8];
    float* out = (float*)d_out;

    void *ph, *ph0, *psup, *prp, *pcnt, *psrc, *pws;
    void *pwth, *pwtl, *pw0h, *pw0l;
    cudaGetSymbolAddress(&ph,   g_h);
    cudaGetSymbolAddress(&ph0,  g_h0);
    cudaGetSymbolAddress(&psup, g_sup);
    cudaGetSymbolAddress(&prp,  g_rowptr);
    cudaGetSymbolAddress(&pcnt, g_cnt);
    cudaGetSymbolAddress(&psrc, g_srcs);
    cudaGetSymbolAddress(&pws,  g_wsort);
    cudaGetSymbolAddress(&pwth, g_wth);
    cudaGetSymbolAddress(&pwtl, g_wtl);
    cudaGetSymbolAddress(&pw0h, g_w0h);
    cudaGetSymbolAddress(&pw0l, g_w0l);
    float* h      = (float*)ph;
    float* h0     = (float*)ph0;
    float* sup    = (float*)psup;
    int*   rowptr = (int*)prp;
    int*   cnt    = (int*)pcnt;
    int*   srcs   = (int*)psrc;
    float* wsort  = (float*)pws;
    __nv_bfloat16* wth = (__nv_bfloat16*)pwth;
    __nv_bfloat16* wtl = (__nv_bfloat16*)pwtl;
    __nv_bfloat16* w0h = (__nv_bfloat16*)pw0h;
    __nv_bfloat16* w0l = (__nv_bfloat16*)pw0l;

    cudaFuncSetAttribute(gemm_mma_kernel,
                         cudaFuncAttributeMaxDynamicSharedMemorySize, GEMM_SMEM);

    // CSR-by-dst build
    zero_cnt_kernel<<<(NN + 255) / 256, 256>>>(cnt);
    hist_kernel    <<<(NE + 255) / 256, 256>>>(edst, cnt);
    scan_kernel    <<<1, 1024>>>(cnt, rowptr);
    scatter_kernel <<<(NE + 255) / 256, 256>>>(esrc, edst, ew, cnt, srcs, wsort);

    // weight transpose + bf16 hi/lo split
    prep_w_kernel<<<(NLAYER * NH * NH + 255) / 256, 256>>>(w0, convw, w0h, w0l, wth, wtl);

    dim3 gg((NN + BM - 1) / BM, NH / BN);
    const int sgrid = (NN + 7) / 8;

    // h = h0 = relu(x @ w0 + b0)
    gemm_mma_kernel<<<gg, 256, GEMM_SMEM>>>(x, NN, NF, w0h, w0l, b0,
                                            nullptr, h, h0, 0.f, 0);

    for (int i = 0; i < NLAYER; ++i) {
        // support = 0.9 * spmm(h) + 0.1 * h0  (two sequential half-feature passes
        // so each pass's gathered h lines stay L2-resident)
        spmm_half_kernel<<<sgrid, 256>>>(rowptr, srcs, wsort, h, h0, sup, 0);
        spmm_half_kernel<<<sgrid, 256>>>(rowptr, srcs, wsort, h, h0, sup, 32);
        float theta = (float)log(0.5 / (double)(i + 1) + 1.0);
        // h = relu(theta*(support@W_i) + (1-theta)*support + h)
        gemm_mma_kernel<<<gg, 256, GEMM_SMEM>>>(sup, NN, NH,
                                                wth + (size_t)i * NH * NH,
                                                wtl + (size_t)i * NH * NH,
                                                nullptr, sup, h, nullptr, theta, 1);
    }

    // out = sigmoid(h @ w1 + b1)
    fc1_kernel<<<(NN + 7) / 8, 128>>>(h, w1, b1, out);
}